// round 3
// baseline (speedup 1.0000x reference)
#include <cuda_runtime.h>
#include <cuda_bf16.h>

// Problem constants: z[100000,128] f32, edge_index int32 [2,1000000] (JAX
// downcasts the requested int64 to int32 with x64 disabled), W1[256,128] f32,
// b1[128], W2[128,1], b2[1]. Output float32 [1000000].
#define MAX_NODES 100000
#define IN_DIM    128
#define OUT_COLS  256   // [U | V] per node

// Scratch: UV[n][0:128] = z[n]@W1[:128] + b1 ; UV[n][128:256] = z[n]@W1[128:]
__device__ float g_uv[(size_t)MAX_NODES * OUT_COLS];

// ---------------------------------------------------------------------------
// Kernel 1: UV = Z @ [W1_top | W1_bot]  (+ b1 folded into first 128 cols)
// BM=64 rows/CTA, full K=128 and N=256 resident in smem (160 KB dynamic).
// ---------------------------------------------------------------------------
#define BM 64
#define GEMM_SMEM ((BM*IN_DIM + IN_DIM*OUT_COLS) * 4)

__global__ __launch_bounds__(256, 1)
void gemm_uv_kernel(const float* __restrict__ z,
                    const float* __restrict__ W1,
                    const float* __restrict__ b1,
                    float* __restrict__ uv,
                    int n_nodes)
{
    extern __shared__ float smem[];
    float* As = smem;                 // [64][128]
    float* Bs = smem + BM * IN_DIM;   // [128][256]

    const int t  = threadIdx.x;
    const int r0 = blockIdx.x * BM;

    // Build Bs[k][j]: j<128 -> W1[k][j] ; j>=128 -> W1[128+k][j-128]
    #pragma unroll 4
    for (int idx = t; idx < IN_DIM * OUT_COLS / 4; idx += 256) {
        int k  = idx >> 6;        // 64 float4s per row
        int jq = idx & 63;
        int j  = jq * 4;
        float4 val;
        if (j < 128) val = *(const float4*)(W1 + k * 128 + j);
        else         val = *(const float4*)(W1 + (128 + k) * 128 + (j - 128));
        *(float4*)(Bs + k * OUT_COLS + j) = val;
    }
    // Load As[row][k] (rows r0..r0+63), zero-pad OOB rows
    #pragma unroll 4
    for (int idx = t; idx < BM * IN_DIM / 4; idx += 256) {
        int row = idx >> 5;       // 32 float4s per row
        int kq  = idx & 31;
        int grow = r0 + row;
        float4 val = make_float4(0.f, 0.f, 0.f, 0.f);
        if (grow < n_nodes) val = *(const float4*)(z + (size_t)grow * IN_DIM + kq * 4);
        *(float4*)(As + row * IN_DIM + kq * 4) = val;
    }
    __syncthreads();

    const int ry = t >> 5;   // warp id 0..7 -> rows ry*8..+8
    const int cx = t & 31;   // lane       -> cols cx*4 (+0 / +128)

    float acc[8][8];
    #pragma unroll
    for (int r = 0; r < 8; r++)
        #pragma unroll
        for (int c = 0; c < 8; c++) acc[r][c] = 0.f;

    const float* aBase = As + (ry * 8) * IN_DIM;

    #pragma unroll 4
    for (int k = 0; k < IN_DIM; k++) {
        float4 b0  = *(const float4*)(Bs + k * OUT_COLS + cx * 4);
        float4 b1v = *(const float4*)(Bs + k * OUT_COLS + 128 + cx * 4);
        #pragma unroll
        for (int r = 0; r < 8; r++) {
            float a = aBase[r * IN_DIM + k];
            acc[r][0] += a * b0.x;  acc[r][1] += a * b0.y;
            acc[r][2] += a * b0.z;  acc[r][3] += a * b0.w;
            acc[r][4] += a * b1v.x; acc[r][5] += a * b1v.y;
            acc[r][6] += a * b1v.z; acc[r][7] += a * b1v.w;
        }
    }

    // Epilogue: fold b1 into U half, store float4s
    float4 bias = *(const float4*)(b1 + cx * 4);
    #pragma unroll
    for (int r = 0; r < 8; r++) {
        int grow = r0 + ry * 8 + r;
        if (grow < n_nodes) {
            float4 o0 = make_float4(acc[r][0] + bias.x, acc[r][1] + bias.y,
                                    acc[r][2] + bias.z, acc[r][3] + bias.w);
            float4 o1 = make_float4(acc[r][4], acc[r][5], acc[r][6], acc[r][7]);
            *(float4*)(uv + (size_t)grow * OUT_COLS + cx * 4)       = o0;
            *(float4*)(uv + (size_t)grow * OUT_COLS + 128 + cx * 4) = o1;
        }
    }
}

// ---------------------------------------------------------------------------
// Kernel 2: per-edge  out[e] = sigmoid( relu(U[src]+V[dst]) . W2 + b2 )
// One warp per edge; lane l handles elements l*4..l*4+3 via float4.
// edge_index is int32 (JAX x64 disabled). Indices clamped defensively.
// ---------------------------------------------------------------------------
__global__ __launch_bounds__(256)
void edge_kernel(const int* __restrict__ ei,
                 const float* __restrict__ uv,
                 const float* __restrict__ W2,
                 const float* __restrict__ b2,
                 float* __restrict__ out,
                 int n_edges, int n_nodes)
{
    int warp = (int)((blockIdx.x * (unsigned)blockDim.x + threadIdx.x) >> 5);
    int lane = threadIdx.x & 31;
    if (warp >= n_edges) return;

    int s = __ldg(&ei[warp]);
    int d = __ldg(&ei[n_edges + warp]);
    s = min(max(s, 0), n_nodes - 1);
    d = min(max(d, 0), n_nodes - 1);

    float4 u = *(const float4*)(uv + (size_t)s * OUT_COLS + lane * 4);
    float4 v = *(const float4*)(uv + (size_t)d * OUT_COLS + 128 + lane * 4);
    float4 w = *(const float4*)(W2 + lane * 4);

    float hx = fmaxf(u.x + v.x, 0.f);
    float hy = fmaxf(u.y + v.y, 0.f);
    float hz = fmaxf(u.z + v.z, 0.f);
    float hw = fmaxf(u.w + v.w, 0.f);

    float acc = hx * w.x + hy * w.y + hz * w.z + hw * w.w;

    acc += __shfl_xor_sync(0xffffffffu, acc, 16);
    acc += __shfl_xor_sync(0xffffffffu, acc, 8);
    acc += __shfl_xor_sync(0xffffffffu, acc, 4);
    acc += __shfl_xor_sync(0xffffffffu, acc, 2);
    acc += __shfl_xor_sync(0xffffffffu, acc, 1);

    if (lane == 0) {
        float x = acc + __ldg(b2);
        out[warp] = 1.f / (1.f + __expf(-x));
    }
}

// ---------------------------------------------------------------------------
extern "C" void kernel_launch(void* const* d_in, const int* in_sizes, int n_in,
                              void* d_out, int out_size)
{
    const float* z  = (const float*)d_in[0];
    const int*   ei = (const int*)d_in[1];
    const float* W1 = (const float*)d_in[2];
    const float* b1 = (const float*)d_in[3];
    const float* W2 = (const float*)d_in[4];
    const float* b2 = (const float*)d_in[5];
    float*       out = (float*)d_out;

    int n_nodes = in_sizes[0] / IN_DIM;
    int n_edges = in_sizes[1] / 2;

    float* uv;
    cudaGetSymbolAddress((void**)&uv, g_uv);

    cudaFuncSetAttribute(gemm_uv_kernel,
                         cudaFuncAttributeMaxDynamicSharedMemorySize, GEMM_SMEM);

    int gemm_blocks = (n_nodes + BM - 1) / BM;
    gemm_uv_kernel<<<gemm_blocks, 256, GEMM_SMEM>>>(z, W1, b1, uv, n_nodes);

    int edge_blocks = (n_edges + 7) / 8;   // 8 warps = 8 edges per block
    edge_kernel<<<edge_blocks, 256>>>(ei, uv, W2, b2, out, n_edges, n_nodes);
}

// round 4
// speedup vs baseline: 1.7616x; 1.7616x over previous
#include <cuda_runtime.h>
#include <cuda_fp16.h>

// z[100000,128] f32, edge_index int32 [2,1000000], W1[256,128] f32, b1[128],
// W2[128,1], b2[1]. Output f32 [1000000].
#define MAX_NODES 100000
#define IN_DIM    128
#define OUT_COLS  256

// UV[n][0:128] = z[n]@W1[:128] + b1 (fp16) ; UV[n][128:256] = z[n]@W1[128:]
__device__ __align__(16) __half g_uvh[(size_t)MAX_NODES * OUT_COLS];
// W1 transposed to n-major fp16: g_w1h[n][k], n in 0..255
__device__ __align__(16) __half g_w1h[256 * 128];

// ---------------------------------------------------------------------------
// Prep: transpose+convert W1 once. block = k (0..127), thread = n (0..255).
// Reads are contiguous per warp; tiny (128 KB total).
// ---------------------------------------------------------------------------
__global__ void prep_w1_kernel(const float* __restrict__ W1)
{
    int k = blockIdx.x;      // 0..127
    int n = threadIdx.x;     // 0..255
    float v = (n < 128) ? W1[k * 128 + n] : W1[(128 + k) * 128 + (n - 128)];
    g_w1h[n * 128 + k] = __float2half(v);
}

// ---------------------------------------------------------------------------
// GEMM: UV = Z @ B (B = [W1_top | W1_bot], n-major fp16), fp32 accum via
// mma.sync.m16n8k16. BM=128 rows/CTA, 512 threads = 16 warps (2 M x 8 N),
// warp tile 64x32. Row stride 136 halves (272B) -> conflict-free LDS.32.
// ---------------------------------------------------------------------------
#define BM        128
#define A_STRIDE  136
#define B_STRIDE  136
#define GEMM_SMEM ((BM * A_STRIDE + OUT_COLS * B_STRIDE) * 2)

__global__ __launch_bounds__(512, 1)
void gemm_uv_mma(const float* __restrict__ z,
                 const float* __restrict__ b1,
                 int n_nodes)
{
    extern __shared__ __half smem[];
    __half* As = smem;                      // [128][136]
    __half* Bs = smem + BM * A_STRIDE;      // [256][136]

    const int t  = threadIdx.x;
    const int r0 = blockIdx.x * BM;

    // Fill Bs[n][k] from g_w1h (coalesced uint4 = 8 halves)
    #pragma unroll
    for (int idx = t; idx < OUT_COLS * 16; idx += 512) {
        int n  = idx >> 4;
        int kq = idx & 15;
        uint4 v = *((const uint4*)(g_w1h + n * 128) + kq);
        *(uint4*)(Bs + n * B_STRIDE + kq * 8) = v;
    }
    // Fill As[row][k]: read z fp32 float4, convert to 4 halves (8B store)
    #pragma unroll
    for (int idx = t; idx < BM * 32; idx += 512) {
        int row  = idx >> 5;
        int kq   = idx & 31;
        int grow = r0 + row;
        float4 v = make_float4(0.f, 0.f, 0.f, 0.f);
        if (grow < n_nodes) v = *(const float4*)(z + (size_t)grow * IN_DIM + kq * 4);
        __half2 h0 = __floats2half2_rn(v.x, v.y);
        __half2 h1 = __floats2half2_rn(v.z, v.w);
        uint2 pk;
        pk.x = *(const unsigned*)&h0;
        pk.y = *(const unsigned*)&h1;
        *(uint2*)(As + row * A_STRIDE + kq * 4) = pk;
    }
    __syncthreads();

    const int wid  = t >> 5;
    const int lane = t & 31;
    const int mw   = (wid & 1) * 64;        // warp M offset (0 / 64)
    const int nw   = (wid >> 1) * 32;       // warp N offset (0..224)
    const int g    = lane >> 2;             // row group 0..7
    const int tig  = lane & 3;              // thread in group

    float acc[4][4][4];                      // [mt][nt][c0..c3]
    #pragma unroll
    for (int mt = 0; mt < 4; mt++)
        #pragma unroll
        for (int nt = 0; nt < 4; nt++)
            #pragma unroll
            for (int c = 0; c < 4; c++) acc[mt][nt][c] = 0.f;

    #pragma unroll
    for (int ks = 0; ks < 8; ks++) {
        // A fragments for 4 m-tiles: regs (m,k),(m+8,k),(m,k+8),(m+8,k+8)
        unsigned a[4][4];
        #pragma unroll
        for (int mt = 0; mt < 4; mt++) {
            const __half* ap = As + (mw + mt * 16 + g) * A_STRIDE + ks * 16 + tig * 2;
            a[mt][0] = *(const unsigned*)(ap);
            a[mt][1] = *(const unsigned*)(ap + 8 * A_STRIDE);
            a[mt][2] = *(const unsigned*)(ap + 8);
            a[mt][3] = *(const unsigned*)(ap + 8 * A_STRIDE + 8);
        }
        #pragma unroll
        for (int nt = 0; nt < 4; nt++) {
            const __half* bp = Bs + (nw + nt * 8 + g) * B_STRIDE + ks * 16 + tig * 2;
            unsigned b0 = *(const unsigned*)(bp);
            unsigned b1r = *(const unsigned*)(bp + 8);
            #pragma unroll
            for (int mt = 0; mt < 4; mt++) {
                asm volatile(
                    "mma.sync.aligned.m16n8k16.row.col.f32.f16.f16.f32 "
                    "{%0,%1,%2,%3}, {%4,%5,%6,%7}, {%8,%9}, {%0,%1,%2,%3};\n"
                    : "+f"(acc[mt][nt][0]), "+f"(acc[mt][nt][1]),
                      "+f"(acc[mt][nt][2]), "+f"(acc[mt][nt][3])
                    : "r"(a[mt][0]), "r"(a[mt][1]), "r"(a[mt][2]), "r"(a[mt][3]),
                      "r"(b0), "r"(b1r));
            }
        }
    }

    // Epilogue: c0,c1 -> (row g, cols n0,n0+1); c2,c3 -> row g+8. Fold b1 (U half).
    #pragma unroll
    for (int nt = 0; nt < 4; nt++) {
        int ncol = nw + nt * 8 + tig * 2;
        float bx = 0.f, by = 0.f;
        if (ncol < 128) { bx = b1[ncol]; by = b1[ncol + 1]; }
        #pragma unroll
        for (int mt = 0; mt < 4; mt++) {
            int row0 = r0 + mw + mt * 16 + g;
            int row1 = row0 + 8;
            if (row0 < n_nodes) {
                __half2 h = __floats2half2_rn(acc[mt][nt][0] + bx, acc[mt][nt][1] + by);
                *(__half2*)(g_uvh + (size_t)row0 * OUT_COLS + ncol) = h;
            }
            if (row1 < n_nodes) {
                __half2 h = __floats2half2_rn(acc[mt][nt][2] + bx, acc[mt][nt][3] + by);
                *(__half2*)(g_uvh + (size_t)row1 * OUT_COLS + ncol) = h;
            }
        }
    }
}

// ---------------------------------------------------------------------------
// Edge kernel: out[e] = sigmoid( relu(U[src]+V[dst]) . W2 + b2 )
// 1 warp/edge; lane loads 4 halves (8B) from each row -> 256B coalesced.
// ---------------------------------------------------------------------------
__global__ __launch_bounds__(256)
void edge_kernel(const int* __restrict__ ei,
                 const float* __restrict__ W2,
                 const float* __restrict__ b2,
                 float* __restrict__ out,
                 int n_edges, int n_nodes)
{
    int warp = (int)((blockIdx.x * (unsigned)blockDim.x + threadIdx.x) >> 5);
    int lane = threadIdx.x & 31;
    if (warp >= n_edges) return;

    int s = __ldg(&ei[warp]);
    int d = __ldg(&ei[n_edges + warp]);
    s = min(max(s, 0), n_nodes - 1);
    d = min(max(d, 0), n_nodes - 1);

    uint2 ub = *(const uint2*)(g_uvh + (size_t)s * OUT_COLS + lane * 4);
    uint2 vb = *(const uint2*)(g_uvh + (size_t)d * OUT_COLS + 128 + lane * 4);
    float4 w = *(const float4*)(W2 + lane * 4);

    float2 u0 = __half22float2(*(const __half2*)&ub.x);
    float2 u1 = __half22float2(*(const __half2*)&ub.y);
    float2 v0 = __half22float2(*(const __half2*)&vb.x);
    float2 v1 = __half22float2(*(const __half2*)&vb.y);

    float hx = fmaxf(u0.x + v0.x, 0.f);
    float hy = fmaxf(u0.y + v0.y, 0.f);
    float hz = fmaxf(u1.x + v1.x, 0.f);
    float hw = fmaxf(u1.y + v1.y, 0.f);

    float acc = hx * w.x + hy * w.y + hz * w.z + hw * w.w;

    acc += __shfl_xor_sync(0xffffffffu, acc, 16);
    acc += __shfl_xor_sync(0xffffffffu, acc, 8);
    acc += __shfl_xor_sync(0xffffffffu, acc, 4);
    acc += __shfl_xor_sync(0xffffffffu, acc, 2);
    acc += __shfl_xor_sync(0xffffffffu, acc, 1);

    if (lane == 0) {
        float x = acc + __ldg(b2);
        out[warp] = 1.f / (1.f + __expf(-x));
    }
}

// ---------------------------------------------------------------------------
extern "C" void kernel_launch(void* const* d_in, const int* in_sizes, int n_in,
                              void* d_out, int out_size)
{
    const float* z  = (const float*)d_in[0];
    const int*   ei = (const int*)d_in[1];
    const float* W1 = (const float*)d_in[2];
    const float* b1 = (const float*)d_in[3];
    const float* W2 = (const float*)d_in[4];
    const float* b2 = (const float*)d_in[5];
    float*       out = (float*)d_out;

    int n_nodes = in_sizes[0] / IN_DIM;
    int n_edges = in_sizes[1] / 2;

    prep_w1_kernel<<<128, 256>>>(W1);

    cudaFuncSetAttribute(gemm_uv_mma,
                         cudaFuncAttributeMaxDynamicSharedMemorySize, GEMM_SMEM);
    int gemm_blocks = (n_nodes + BM - 1) / BM;
    gemm_uv_mma<<<gemm_blocks, 512, GEMM_SMEM>>>(z, b1, n_nodes);

    int edge_blocks = (n_edges + 7) / 8;   // 8 warps = 8 edges per block
    edge_kernel<<<edge_blocks, 256>>>(ei, W2, b2, out, n_edges, n_nodes);
}

// round 5
// speedup vs baseline: 2.0205x; 1.1470x over previous
#include <cuda_runtime.h>
#include <cuda_fp16.h>

// z[100000,128] f32, edge_index int32 [2,1000000], W1[256,128] f32, b1[128],
// W2[128,1], b2[1]. Output f32 [1000000].
#define MAX_NODES 100000
#define IN_DIM    128
#define OUT_COLS  256

// UV[n][0:128] = z[n]@W1[:128] + b1 (fp16) ; UV[n][128:256] = z[n]@W1[128:]
__device__ __align__(16) __half g_uvh[(size_t)MAX_NODES * OUT_COLS];

// ---------------------------------------------------------------------------
// GEMM: UV_half = Z @ W1_half (n-major fp16 in smem), fp32 accum via
// mma.sync.m16n8k16. grid = (node_tiles, 2): blockIdx.y selects U / V half.
// BM=128 rows/CTA, N=128 cols/CTA, 256 threads = 8 warps (2 M x 4 N),
// warp tile 64x32. Row stride 136 halves (272B) -> conflict-free LDS.32.
// Smem 68KB -> 2-3 CTAs/SM co-resident (fill/compute overlap across CTAs).
// ---------------------------------------------------------------------------
#define BM        128
#define BN        128
#define A_STRIDE  136
#define B_STRIDE  136
#define GEMM_SMEM ((BM * A_STRIDE + BN * B_STRIDE) * 2)

__global__ __launch_bounds__(256)
void gemm_uv_mma(const float* __restrict__ z,
                 const float* __restrict__ W1,
                 const float* __restrict__ b1,
                 int n_nodes)
{
    extern __shared__ __half smem[];
    __half* As = smem;                      // [128][136]
    __half* Bs = smem + BM * A_STRIDE;      // [128][136]  Bs[n][k] = W1h[k][n]

    const int t    = threadIdx.x;
    const int r0   = blockIdx.x * BM;
    const int half = blockIdx.y;            // 0 = U (rows 0-127 of W1), 1 = V

    // Fill Bs[n][k] from W1 half: coalesced float4 gmem reads (thread covers
    // k row, 4 consecutive n), transposed STS.16 stores (4-way conflict, cheap).
    const float* w1base = W1 + (size_t)half * 128 * 128;
    #pragma unroll
    for (int idx = t; idx < 128 * 32; idx += 256) {
        int k  = idx >> 5;
        int nq = idx & 31;
        float4 v = *(const float4*)(w1base + k * 128 + nq * 4);
        Bs[(nq * 4 + 0) * B_STRIDE + k] = __float2half(v.x);
        Bs[(nq * 4 + 1) * B_STRIDE + k] = __float2half(v.y);
        Bs[(nq * 4 + 2) * B_STRIDE + k] = __float2half(v.z);
        Bs[(nq * 4 + 3) * B_STRIDE + k] = __float2half(v.w);
    }
    // Fill As[row][k]: read z fp32 float4, convert to 4 halves (8B store)
    #pragma unroll
    for (int idx = t; idx < BM * 32; idx += 256) {
        int row  = idx >> 5;
        int kq   = idx & 31;
        int grow = r0 + row;
        float4 v = make_float4(0.f, 0.f, 0.f, 0.f);
        if (grow < n_nodes) v = *(const float4*)(z + (size_t)grow * IN_DIM + kq * 4);
        __half2 h0 = __floats2half2_rn(v.x, v.y);
        __half2 h1 = __floats2half2_rn(v.z, v.w);
        uint2 pk;
        pk.x = *(const unsigned*)&h0;
        pk.y = *(const unsigned*)&h1;
        *(uint2*)(As + row * A_STRIDE + kq * 4) = pk;
    }
    __syncthreads();

    const int wid  = t >> 5;
    const int lane = t & 31;
    const int mw   = (wid & 1) * 64;        // warp M offset (0 / 64)
    const int nw   = (wid >> 1) * 32;       // warp N offset (0..96)
    const int g    = lane >> 2;             // row group 0..7
    const int tig  = lane & 3;              // thread in group

    float acc[4][4][4];                      // [mt][nt][c0..c3]
    #pragma unroll
    for (int mt = 0; mt < 4; mt++)
        #pragma unroll
        for (int nt = 0; nt < 4; nt++)
            #pragma unroll
            for (int c = 0; c < 4; c++) acc[mt][nt][c] = 0.f;

    #pragma unroll
    for (int ks = 0; ks < 8; ks++) {
        unsigned a[4][4];
        #pragma unroll
        for (int mt = 0; mt < 4; mt++) {
            const __half* ap = As + (mw + mt * 16 + g) * A_STRIDE + ks * 16 + tig * 2;
            a[mt][0] = *(const unsigned*)(ap);
            a[mt][1] = *(const unsigned*)(ap + 8 * A_STRIDE);
            a[mt][2] = *(const unsigned*)(ap + 8);
            a[mt][3] = *(const unsigned*)(ap + 8 * A_STRIDE + 8);
        }
        #pragma unroll
        for (int nt = 0; nt < 4; nt++) {
            const __half* bp = Bs + (nw + nt * 8 + g) * B_STRIDE + ks * 16 + tig * 2;
            unsigned b0  = *(const unsigned*)(bp);
            unsigned b1r = *(const unsigned*)(bp + 8);
            #pragma unroll
            for (int mt = 0; mt < 4; mt++) {
                asm volatile(
                    "mma.sync.aligned.m16n8k16.row.col.f32.f16.f16.f32 "
                    "{%0,%1,%2,%3}, {%4,%5,%6,%7}, {%8,%9}, {%0,%1,%2,%3};\n"
                    : "+f"(acc[mt][nt][0]), "+f"(acc[mt][nt][1]),
                      "+f"(acc[mt][nt][2]), "+f"(acc[mt][nt][3])
                    : "r"(a[mt][0]), "r"(a[mt][1]), "r"(a[mt][2]), "r"(a[mt][3]),
                      "r"(b0), "r"(b1r));
            }
        }
    }

    // Epilogue: c0,c1 -> (row g, cols n,n+1); c2,c3 -> row g+8. b1 only on U half.
    #pragma unroll
    for (int nt = 0; nt < 4; nt++) {
        int ncol = nw + nt * 8 + tig * 2;
        float bx = 0.f, by = 0.f;
        if (half == 0) { bx = b1[ncol]; by = b1[ncol + 1]; }
        int ocol = half * 128 + ncol;
        #pragma unroll
        for (int mt = 0; mt < 4; mt++) {
            int row0 = r0 + mw + mt * 16 + g;
            int row1 = row0 + 8;
            if (row0 < n_nodes) {
                __half2 h = __floats2half2_rn(acc[mt][nt][0] + bx, acc[mt][nt][1] + by);
                *(__half2*)(g_uvh + (size_t)row0 * OUT_COLS + ocol) = h;
            }
            if (row1 < n_nodes) {
                __half2 h = __floats2half2_rn(acc[mt][nt][2] + bx, acc[mt][nt][3] + by);
                *(__half2*)(g_uvh + (size_t)row1 * OUT_COLS + ocol) = h;
            }
        }
    }
}

// ---------------------------------------------------------------------------
// Edge kernel: out[e] = sigmoid( relu(U[src]+V[dst]) . W2 + b2 )
// 2 edges per warp: lanes 0-15 -> edge 2w, lanes 16-31 -> edge 2w+1.
// Each lane loads uint4 (8 halves) from U and V rows -> 256B coalesced per row,
// half the instruction issue / warp count of the 1-edge-per-warp version.
// ---------------------------------------------------------------------------
__global__ __launch_bounds__(256)
void edge_kernel(const int* __restrict__ ei,
                 const float* __restrict__ W2,
                 const float* __restrict__ b2,
                 float* __restrict__ out,
                 int n_edges, int n_nodes)
{
    int warp = (int)((blockIdx.x * (unsigned)blockDim.x + threadIdx.x) >> 5);
    int lane = threadIdx.x & 31;
    int half = lane >> 4;           // which edge of the pair
    int l    = lane & 15;           // lane within edge group

    int e = warp * 2 + half;
    if (e >= n_edges) return;

    int s = __ldg(&ei[e]);
    int d = __ldg(&ei[n_edges + e]);
    s = min(max(s, 0), n_nodes - 1);
    d = min(max(d, 0), n_nodes - 1);

    uint4 ub = *(const uint4*)(g_uvh + (size_t)s * OUT_COLS + l * 8);
    uint4 vb = *(const uint4*)(g_uvh + (size_t)d * OUT_COLS + 128 + l * 8);
    float4 w0 = *(const float4*)(W2 + l * 8);
    float4 w1 = *(const float4*)(W2 + l * 8 + 4);

    float2 u0 = __half22float2(*(const __half2*)&ub.x);
    float2 u1 = __half22float2(*(const __half2*)&ub.y);
    float2 u2 = __half22float2(*(const __half2*)&ub.z);
    float2 u3 = __half22float2(*(const __half2*)&ub.w);
    float2 v0 = __half22float2(*(const __half2*)&vb.x);
    float2 v1 = __half22float2(*(const __half2*)&vb.y);
    float2 v2 = __half22float2(*(const __half2*)&vb.z);
    float2 v3 = __half22float2(*(const __half2*)&vb.w);

    float acc;
    acc  = fmaxf(u0.x + v0.x, 0.f) * w0.x;
    acc += fmaxf(u0.y + v0.y, 0.f) * w0.y;
    acc += fmaxf(u1.x + v1.x, 0.f) * w0.z;
    acc += fmaxf(u1.y + v1.y, 0.f) * w0.w;
    acc += fmaxf(u2.x + v2.x, 0.f) * w1.x;
    acc += fmaxf(u2.y + v2.y, 0.f) * w1.y;
    acc += fmaxf(u3.x + v3.x, 0.f) * w1.z;
    acc += fmaxf(u3.y + v3.y, 0.f) * w1.w;

    // reduce over 16 lanes (xor offsets stay within the 16-lane group)
    acc += __shfl_xor_sync(0xffffffffu, acc, 8);
    acc += __shfl_xor_sync(0xffffffffu, acc, 4);
    acc += __shfl_xor_sync(0xffffffffu, acc, 2);
    acc += __shfl_xor_sync(0xffffffffu, acc, 1);

    if (l == 0) {
        float x = acc + __ldg(b2);
        out[e] = 1.f / (1.f + __expf(-x));
    }
}

// ---------------------------------------------------------------------------
extern "C" void kernel_launch(void* const* d_in, const int* in_sizes, int n_in,
                              void* d_out, int out_size)
{
    const float* z  = (const float*)d_in[0];
    const int*   ei = (const int*)d_in[1];
    const float* W1 = (const float*)d_in[2];
    const float* b1 = (const float*)d_in[3];
    const float* W2 = (const float*)d_in[4];
    const float* b2 = (const float*)d_in[5];
    float*       out = (float*)d_out;

    int n_nodes = in_sizes[0] / IN_DIM;
    int n_edges = in_sizes[1] / 2;

    cudaFuncSetAttribute(gemm_uv_mma,
                         cudaFuncAttributeMaxDynamicSharedMemorySize, GEMM_SMEM);
    dim3 gemm_grid((n_nodes + BM - 1) / BM, 2);
    gemm_uv_mma<<<gemm_grid, 256, GEMM_SMEM>>>(z, W1, b1, n_nodes);

    // 2 edges per warp, 8 warps per block -> 16 edges per block
    int edge_blocks = (n_edges + 15) / 16;
    edge_kernel<<<edge_blocks, 256>>>(ei, W2, b2, out, n_edges, n_nodes);
}

// round 6
// speedup vs baseline: 2.1185x; 1.0485x over previous
#include <cuda_runtime.h>
#include <cuda_fp16.h>

// z[100000,128] f32, edge_index int32 [2,1000000], W1[256,128] f32, b1[128],
// W2[128,1], b2[1]. Output f32 [1000000].
#define MAX_NODES 100000
#define IN_DIM    128
#define OUT_COLS  256

// UV[n][0:128] = z[n]@W1[:128] + b1 (fp16) ; UV[n][128:256] = z[n]@W1[128:]
__device__ __align__(16) __half g_uvh[(size_t)MAX_NODES * OUT_COLS];

// ---------------------------------------------------------------------------
// GEMM: UV_half = Z @ W1_half (n-major fp16 in smem), fp32 accum via
// mma.sync.m16n8k16. grid = (node_tiles, 2): blockIdx.y selects U / V half.
// BM=128 rows/CTA, N=128 cols/CTA, 256 threads = 8 warps (2 M x 4 N),
// warp tile 64x32. Row stride 136 halves (272B) -> conflict-free LDS.32.
// ---------------------------------------------------------------------------
#define BM        128
#define BN        128
#define A_STRIDE  136
#define B_STRIDE  136
#define GEMM_SMEM ((BM * A_STRIDE + BN * B_STRIDE) * 2)

__global__ __launch_bounds__(256, 2)
void gemm_uv_mma(const float* __restrict__ z,
                 const float* __restrict__ W1,
                 const float* __restrict__ b1,
                 int n_nodes)
{
    extern __shared__ __half smem[];
    __half* As = smem;                      // [128][136]
    __half* Bs = smem + BM * A_STRIDE;      // [128][136]  Bs[n][k] = W1h[k][n]

    const int t    = threadIdx.x;
    const int r0   = blockIdx.x * BM;
    const int half = blockIdx.y;            // 0 = U half of W1, 1 = V half

    // Fill As[row][k] FIRST (long-latency z reads issue early):
    // read z fp32 float4, convert to 4 halves (8B store)
    #pragma unroll
    for (int idx = t; idx < BM * 32; idx += 256) {
        int row  = idx >> 5;
        int kq   = idx & 31;
        int grow = r0 + row;
        float4 v = make_float4(0.f, 0.f, 0.f, 0.f);
        if (grow < n_nodes) v = *(const float4*)(z + (size_t)grow * IN_DIM + kq * 4);
        __half2 h0 = __floats2half2_rn(v.x, v.y);
        __half2 h1 = __floats2half2_rn(v.z, v.w);
        uint2 pk;
        pk.x = *(const unsigned*)&h0;
        pk.y = *(const unsigned*)&h1;
        *(uint2*)(As + row * A_STRIDE + kq * 4) = pk;
    }
    // Fill Bs[n][k] from W1 half (L2-resident after wave 1): coalesced float4
    // reads, transposed STS.16 stores (4-way conflict, small volume).
    const float* w1base = W1 + (size_t)half * 128 * 128;
    #pragma unroll
    for (int idx = t; idx < 128 * 32; idx += 256) {
        int k  = idx >> 5;
        int nq = idx & 31;
        float4 v = *(const float4*)(w1base + k * 128 + nq * 4);
        Bs[(nq * 4 + 0) * B_STRIDE + k] = __float2half(v.x);
        Bs[(nq * 4 + 1) * B_STRIDE + k] = __float2half(v.y);
        Bs[(nq * 4 + 2) * B_STRIDE + k] = __float2half(v.z);
        Bs[(nq * 4 + 3) * B_STRIDE + k] = __float2half(v.w);
    }
    __syncthreads();

    const int wid  = t >> 5;
    const int lane = t & 31;
    const int mw   = (wid & 1) * 64;        // warp M offset (0 / 64)
    const int nw   = (wid >> 1) * 32;       // warp N offset (0..96)
    const int g    = lane >> 2;             // row group 0..7
    const int tig  = lane & 3;              // thread in group

    float acc[4][4][4];                      // [mt][nt][c0..c3]
    #pragma unroll
    for (int mt = 0; mt < 4; mt++)
        #pragma unroll
        for (int nt = 0; nt < 4; nt++)
            #pragma unroll
            for (int c = 0; c < 4; c++) acc[mt][nt][c] = 0.f;

    #pragma unroll
    for (int ks = 0; ks < 8; ks++) {
        unsigned a[4][4];
        #pragma unroll
        for (int mt = 0; mt < 4; mt++) {
            const __half* ap = As + (mw + mt * 16 + g) * A_STRIDE + ks * 16 + tig * 2;
            a[mt][0] = *(const unsigned*)(ap);
            a[mt][1] = *(const unsigned*)(ap + 8 * A_STRIDE);
            a[mt][2] = *(const unsigned*)(ap + 8);
            a[mt][3] = *(const unsigned*)(ap + 8 * A_STRIDE + 8);
        }
        #pragma unroll
        for (int nt = 0; nt < 4; nt++) {
            const __half* bp = Bs + (nw + nt * 8 + g) * B_STRIDE + ks * 16 + tig * 2;
            unsigned b0  = *(const unsigned*)(bp);
            unsigned b1r = *(const unsigned*)(bp + 8);
            #pragma unroll
            for (int mt = 0; mt < 4; mt++) {
                asm volatile(
                    "mma.sync.aligned.m16n8k16.row.col.f32.f16.f16.f32 "
                    "{%0,%1,%2,%3}, {%4,%5,%6,%7}, {%8,%9}, {%0,%1,%2,%3};\n"
                    : "+f"(acc[mt][nt][0]), "+f"(acc[mt][nt][1]),
                      "+f"(acc[mt][nt][2]), "+f"(acc[mt][nt][3])
                    : "r"(a[mt][0]), "r"(a[mt][1]), "r"(a[mt][2]), "r"(a[mt][3]),
                      "r"(b0), "r"(b1r));
            }
        }
    }

    // Epilogue: c0,c1 -> (row g, cols n,n+1); c2,c3 -> row g+8. b1 only on U half.
    #pragma unroll
    for (int nt = 0; nt < 4; nt++) {
        int ncol = nw + nt * 8 + tig * 2;
        float bx = 0.f, by = 0.f;
        if (half == 0) { bx = b1[ncol]; by = b1[ncol + 1]; }
        int ocol = half * 128 + ncol;
        #pragma unroll
        for (int mt = 0; mt < 4; mt++) {
            int row0 = r0 + mw + mt * 16 + g;
            int row1 = row0 + 8;
            if (row0 < n_nodes) {
                __half2 h = __floats2half2_rn(acc[mt][nt][0] + bx, acc[mt][nt][1] + by);
                *(__half2*)(g_uvh + (size_t)row0 * OUT_COLS + ocol) = h;
            }
            if (row1 < n_nodes) {
                __half2 h = __floats2half2_rn(acc[mt][nt][2] + bx, acc[mt][nt][3] + by);
                *(__half2*)(g_uvh + (size_t)row1 * OUT_COLS + ocol) = h;
            }
        }
    }
}

// ---------------------------------------------------------------------------
// Edge kernel (persistent): out[e] = sigmoid( relu(U[src]+V[dst]) . W2 + b2 )
// Fixed grid; each warp grid-strides over edge-pairs. W2 fragment + b2 are
// loaded ONCE per thread (register-resident) instead of per edge -> removes
// the dominant share of loop-invariant L1 wavefronts seen in R5 ncu.
// 2 edges/warp/iter: lanes 0-15 -> edge e0, lanes 16-31 -> edge e0+1.
// ---------------------------------------------------------------------------
#define EDGE_BLOCKS 1184   // 148 SM x 8 CTAs (256 thr) = 2048 thr/SM

__global__ __launch_bounds__(256)
void edge_kernel(const int* __restrict__ ei,
                 const float* __restrict__ W2,
                 const float* __restrict__ b2,
                 float* __restrict__ out,
                 int n_edges, int n_nodes)
{
    const int lane = threadIdx.x & 31;
    const int half = lane >> 4;          // which edge of the pair
    const int l    = lane & 15;          // lane within 16-lane edge group

    // Loop-invariant: W2 fragment (8 floats) + bias, register-resident.
    const float4 w0   = *(const float4*)(W2 + l * 8);
    const float4 w1   = *(const float4*)(W2 + l * 8 + 4);
    const float  bias = __ldg(b2);

    const int warp_g  = (int)((blockIdx.x * (unsigned)blockDim.x + threadIdx.x) >> 5);
    const int n_warps = (EDGE_BLOCKS * 256) >> 5;

    for (int e0 = warp_g * 2; e0 < n_edges; e0 += n_warps * 2) {
        int e     = e0 + half;
        bool vld  = (e < n_edges);
        int eload = vld ? e : (n_edges - 1);

        int s = __ldg(&ei[eload]);
        int d = __ldg(&ei[n_edges + eload]);
        s = min(max(s, 0), n_nodes - 1);
        d = min(max(d, 0), n_nodes - 1);

        uint4 ub = *(const uint4*)(g_uvh + (size_t)s * OUT_COLS + l * 8);
        uint4 vb = *(const uint4*)(g_uvh + (size_t)d * OUT_COLS + 128 + l * 8);

        float2 u0 = __half22float2(*(const __half2*)&ub.x);
        float2 u1 = __half22float2(*(const __half2*)&ub.y);
        float2 u2 = __half22float2(*(const __half2*)&ub.z);
        float2 u3 = __half22float2(*(const __half2*)&ub.w);
        float2 v0 = __half22float2(*(const __half2*)&vb.x);
        float2 v1 = __half22float2(*(const __half2*)&vb.y);
        float2 v2 = __half22float2(*(const __half2*)&vb.z);
        float2 v3 = __half22float2(*(const __half2*)&vb.w);

        float acc;
        acc  = fmaxf(u0.x + v0.x, 0.f) * w0.x;
        acc += fmaxf(u0.y + v0.y, 0.f) * w0.y;
        acc += fmaxf(u1.x + v1.x, 0.f) * w0.z;
        acc += fmaxf(u1.y + v1.y, 0.f) * w0.w;
        acc += fmaxf(u2.x + v2.x, 0.f) * w1.x;
        acc += fmaxf(u2.y + v2.y, 0.f) * w1.y;
        acc += fmaxf(u3.x + v3.x, 0.f) * w1.z;
        acc += fmaxf(u3.y + v3.y, 0.f) * w1.w;

        // reduce over 16 lanes (xor offsets stay within the 16-lane group)
        acc += __shfl_xor_sync(0xffffffffu, acc, 8);
        acc += __shfl_xor_sync(0xffffffffu, acc, 4);
        acc += __shfl_xor_sync(0xffffffffu, acc, 2);
        acc += __shfl_xor_sync(0xffffffffu, acc, 1);

        if (l == 0 && vld) {
            float x = acc + bias;
            out[e] = 1.f / (1.f + __expf(-x));
        }
    }
}

// ---------------------------------------------------------------------------
extern "C" void kernel_launch(void* const* d_in, const int* in_sizes, int n_in,
                              void* d_out, int out_size)
{
    const float* z  = (const float*)d_in[0];
    const int*   ei = (const int*)d_in[1];
    const float* W1 = (const float*)d_in[2];
    const float* b1 = (const float*)d_in[3];
    const float* W2 = (const float*)d_in[4];
    const float* b2 = (const float*)d_in[5];
    float*       out = (float*)d_out;

    int n_nodes = in_sizes[0] / IN_DIM;
    int n_edges = in_sizes[1] / 2;

    cudaFuncSetAttribute(gemm_uv_mma,
                         cudaFuncAttributeMaxDynamicSharedMemorySize, GEMM_SMEM);
    dim3 gemm_grid((n_nodes + BM - 1) / BM, 2);
    gemm_uv_mma<<<gemm_grid, 256, GEMM_SMEM>>>(z, W1, b1, n_nodes);

    edge_kernel<<<EDGE_BLOCKS, 256>>>(ei, W2, b2, out, n_edges, n_nodes);
}

// round 8
// speedup vs baseline: 2.1690x; 1.0239x over previous
#include <cuda_runtime.h>
#include <cuda_fp16.h>
#include <cstdint>

// z[100000,128] f32, edge_index int32 [2,1000000], W1[256,128] f32, b1[128],
// W2[128,1], b2[1]. Output f32 [1000000].
#define MAX_NODES 100000
#define IN_DIM    128
#define OUT_COLS  256

// UV[n][0:128] = z[n]@W1[:128] + b1 (fp16) ; UV[n][128:256] = z[n]@W1[128:]
__device__ __align__(16) __half g_uvh[(size_t)MAX_NODES * OUT_COLS];

// ---------------------------------------------------------------------------
// GEMM: UV_half = Z @ W1_half (n-major fp16 in smem), fp32 accum via
// mma.sync.m16n8k16. grid = (node_tiles, 2): blockIdx.y selects U / V half.
// BM=128 rows/CTA, N=128 cols/CTA, 256 threads = 8 warps (2 M x 4 N),
// warp tile 64x32. Row stride 136 halves (272B): ldmatrix rows r -> banks
// 4r..4r+3 -> 8 rows cover all 32 banks, conflict-free LDSM.
// Fragment fetch via ldmatrix.m8n8.x4: 6 LDSM/warp/ks vs 24 LDS.32 in R6.
// ---------------------------------------------------------------------------
#define BM        128
#define BN        128
#define A_STRIDE  136
#define B_STRIDE  136
#define GEMM_SMEM ((BM * A_STRIDE + BN * B_STRIDE) * 2)

__device__ __forceinline__ uint32_t smem_to_u32(const void* p) {
    uint32_t a;
    asm("{ .reg .u64 t; cvta.to.shared.u64 t, %1; cvt.u32.u64 %0, t; }"
        : "=r"(a) : "l"(p));
    return a;
}

#define LDMATRIX_X4(r0, r1, r2, r3, addr) \
    asm volatile("ldmatrix.sync.aligned.m8n8.x4.shared.b16 {%0,%1,%2,%3}, [%4];" \
                 : "=r"(r0), "=r"(r1), "=r"(r2), "=r"(r3) : "r"(addr))

__global__ __launch_bounds__(256, 2)
void gemm_uv_mma(const float* __restrict__ z,
                 const float* __restrict__ W1,
                 const float* __restrict__ b1,
                 int n_nodes)
{
    extern __shared__ __half smem[];
    __half* As = smem;                      // [128][136]
    __half* Bs = smem + BM * A_STRIDE;      // [128][136]  Bs[n][k] = W1h[k][n]

    const int t    = threadIdx.x;
    const int r0   = blockIdx.x * BM;
    const int half = blockIdx.y;            // 0 = U half of W1, 1 = V half

    // Fill As[row][k] FIRST (long-latency z reads issue early)
    #pragma unroll
    for (int idx = t; idx < BM * 32; idx += 256) {
        int row  = idx >> 5;
        int kq   = idx & 31;
        int grow = r0 + row;
        float4 v = make_float4(0.f, 0.f, 0.f, 0.f);
        if (grow < n_nodes) v = *(const float4*)(z + (size_t)grow * IN_DIM + kq * 4);
        __half2 h0 = __floats2half2_rn(v.x, v.y);
        __half2 h1 = __floats2half2_rn(v.z, v.w);
        uint2 pk;
        pk.x = *(const unsigned*)&h0;
        pk.y = *(const unsigned*)&h1;
        *(uint2*)(As + row * A_STRIDE + kq * 4) = pk;
    }
    // Fill Bs[n][k] from W1 half (L2-resident after wave 1)
    const float* w1base = W1 + (size_t)half * 128 * 128;
    #pragma unroll
    for (int idx = t; idx < 128 * 32; idx += 256) {
        int k  = idx >> 5;
        int nq = idx & 31;
        float4 v = *(const float4*)(w1base + k * 128 + nq * 4);
        Bs[(nq * 4 + 0) * B_STRIDE + k] = __float2half(v.x);
        Bs[(nq * 4 + 1) * B_STRIDE + k] = __float2half(v.y);
        Bs[(nq * 4 + 2) * B_STRIDE + k] = __float2half(v.z);
        Bs[(nq * 4 + 3) * B_STRIDE + k] = __float2half(v.w);
    }
    __syncthreads();

    const int wid  = t >> 5;
    const int lane = t & 31;
    const int mw   = (wid & 1) * 64;        // warp M offset (0 / 64)
    const int nw   = (wid >> 1) * 32;       // warp N offset (0..96)
    const int g    = lane >> 2;             // row group 0..7
    const int tig  = lane & 3;              // thread in group

    // ldmatrix source rows/cols for this lane (shared by A and B tiles):
    // lanes 0-15 -> rows +0..15 (col byte +0), lanes 16-31 -> rows 0..15 (col +16B)
    const int lrow = lane & 15;
    const int lcol = (lane >> 4) * 16;      // byte offset within 32B k-slice

    const uint32_t As_b = smem_to_u32(As);
    const uint32_t Bs_b = smem_to_u32(Bs);

    float acc[4][4][4];                      // [mt][nt][c0..c3]
    #pragma unroll
    for (int mt = 0; mt < 4; mt++)
        #pragma unroll
        for (int nt = 0; nt < 4; nt++)
            #pragma unroll
            for (int c = 0; c < 4; c++) acc[mt][nt][c] = 0.f;

    #pragma unroll
    for (int ks = 0; ks < 8; ks++) {
        // A fragments: 4 LDSM.x4, regs = (m,k),(m+8,k),(m,k+8),(m+8,k+8)
        unsigned a[4][4];
        #pragma unroll
        for (int mt = 0; mt < 4; mt++) {
            uint32_t addr = As_b + (uint32_t)(mw + mt * 16 + lrow) * (A_STRIDE * 2)
                          + ks * 32 + lcol;
            LDMATRIX_X4(a[mt][0], a[mt][1], a[mt][2], a[mt][3], addr);
        }
        // B fragments: 2 LDSM.x4 cover 4 nt tiles (b0 rows 0-7 / 8-15, b1 +8 cols)
        unsigned bf[4][2];
        #pragma unroll
        for (int ntp = 0; ntp < 2; ntp++) {
            uint32_t addr = Bs_b + (uint32_t)(nw + ntp * 16 + lrow) * (B_STRIDE * 2)
                          + ks * 32 + lcol;
            unsigned q0, q1, q2, q3;
            LDMATRIX_X4(q0, q1, q2, q3, addr);
            bf[ntp * 2 + 0][0] = q0; bf[ntp * 2 + 1][0] = q1;
            bf[ntp * 2 + 0][1] = q2; bf[ntp * 2 + 1][1] = q3;
        }
        #pragma unroll
        for (int nt = 0; nt < 4; nt++) {
            #pragma unroll
            for (int mt = 0; mt < 4; mt++) {
                asm volatile(
                    "mma.sync.aligned.m16n8k16.row.col.f32.f16.f16.f32 "
                    "{%0,%1,%2,%3}, {%4,%5,%6,%7}, {%8,%9}, {%0,%1,%2,%3};\n"
                    : "+f"(acc[mt][nt][0]), "+f"(acc[mt][nt][1]),
                      "+f"(acc[mt][nt][2]), "+f"(acc[mt][nt][3])
                    : "r"(a[mt][0]), "r"(a[mt][1]), "r"(a[mt][2]), "r"(a[mt][3]),
                      "r"(bf[nt][0]), "r"(bf[nt][1]));
            }
        }
    }

    // Epilogue: c0,c1 -> (row g, cols n,n+1); c2,c3 -> row g+8. b1 only on U half.
    #pragma unroll
    for (int nt = 0; nt < 4; nt++) {
        int ncol = nw + nt * 8 + tig * 2;
        float bx = 0.f, by = 0.f;
        if (half == 0) { bx = b1[ncol]; by = b1[ncol + 1]; }
        int ocol = half * 128 + ncol;
        #pragma unroll
        for (int mt = 0; mt < 4; mt++) {
            int row0 = r0 + mw + mt * 16 + g;
            int row1 = row0 + 8;
            if (row0 < n_nodes) {
                __half2 h = __floats2half2_rn(acc[mt][nt][0] + bx, acc[mt][nt][1] + by);
                *(__half2*)(g_uvh + (size_t)row0 * OUT_COLS + ocol) = h;
            }
            if (row1 < n_nodes) {
                __half2 h = __floats2half2_rn(acc[mt][nt][2] + bx, acc[mt][nt][3] + by);
                *(__half2*)(g_uvh + (size_t)row1 * OUT_COLS + ocol) = h;
            }
        }
    }
}

// ---------------------------------------------------------------------------
// Edge kernel (persistent): out[e] = sigmoid( relu(U[src]+V[dst]) . W2 + b2 )
// W2 fragment + b2 register-resident (loop-invariant). half2 HADD2/HMAX2 for
// add+relu (2 elems/instr); fp32 conversion only for the final dot.
// 2 edges/warp/iter: lanes 0-15 -> e0, lanes 16-31 -> e0+1.
// ---------------------------------------------------------------------------
#define EDGE_BLOCKS 1184   // 148 SM x 8 CTAs (256 thr)

__global__ __launch_bounds__(256)
void edge_kernel(const int* __restrict__ ei,
                 const float* __restrict__ W2,
                 const float* __restrict__ b2,
                 float* __restrict__ out,
                 int n_edges, int n_nodes)
{
    const int lane = threadIdx.x & 31;
    const int half = lane >> 4;          // which edge of the pair
    const int l    = lane & 15;          // lane within 16-lane edge group

    const float4 w0   = *(const float4*)(W2 + l * 8);
    const float4 w1   = *(const float4*)(W2 + l * 8 + 4);
    const float  bias = __ldg(b2);
    const __half2 zero2 = __float2half2_rn(0.f);

    const int warp_g  = (int)((blockIdx.x * (unsigned)blockDim.x + threadIdx.x) >> 5);
    const int n_warps = (EDGE_BLOCKS * 256) >> 5;

    for (int e0 = warp_g * 2; e0 < n_edges; e0 += n_warps * 2) {
        int e     = e0 + half;
        bool vld  = (e < n_edges);
        int eload = vld ? e : (n_edges - 1);

        int s = __ldg(&ei[eload]);
        int d = __ldg(&ei[n_edges + eload]);
        s = min(max(s, 0), n_nodes - 1);
        d = min(max(d, 0), n_nodes - 1);

        uint4 ub = *(const uint4*)(g_uvh + (size_t)s * OUT_COLS + l * 8);
        uint4 vb = *(const uint4*)(g_uvh + (size_t)d * OUT_COLS + 128 + l * 8);

        __half2 h0 = __hmax2(__hadd2(*(__half2*)&ub.x, *(__half2*)&vb.x), zero2);
        __half2 h1 = __hmax2(__hadd2(*(__half2*)&ub.y, *(__half2*)&vb.y), zero2);
        __half2 h2 = __hmax2(__hadd2(*(__half2*)&ub.z, *(__half2*)&vb.z), zero2);
        __half2 h3 = __hmax2(__hadd2(*(__half2*)&ub.w, *(__half2*)&vb.w), zero2);

        float2 f0 = __half22float2(h0);
        float2 f1 = __half22float2(h1);
        float2 f2 = __half22float2(h2);
        float2 f3 = __half22float2(h3);

        float acc;
        acc  = f0.x * w0.x + f0.y * w0.y;
        acc += f1.x * w0.z + f1.y * w0.w;
        acc += f2.x * w1.x + f2.y * w1.y;
        acc += f3.x * w1.z + f3.y * w1.w;

        acc += __shfl_xor_sync(0xffffffffu, acc, 8);
        acc += __shfl_xor_sync(0xffffffffu, acc, 4);
        acc += __shfl_xor_sync(0xffffffffu, acc, 2);
        acc += __shfl_xor_sync(0xffffffffu, acc, 1);

        if (l == 0 && vld) {
            float x = acc + bias;
            out[e] = 1.f / (1.f + __expf(-x));
        }
    }
}

// ---------------------------------------------------------------------------
extern "C" void kernel_launch(void* const* d_in, const int* in_sizes, int n_in,
                              void* d_out, int out_size)
{
    const float* z  = (const float*)d_in[0];
    const int*   ei = (const int*)d_in[1];
    const float* W1 = (const float*)d_in[2];
    const float* b1 = (const float*)d_in[3];
    const float* W2 = (const float*)d_in[4];
    const float* b2 = (const float*)d_in[5];
    float*       out = (float*)d_out;

    int n_nodes = in_sizes[0] / IN_DIM;
    int n_edges = in_sizes[1] / 2;

    cudaFuncSetAttribute(gemm_uv_mma,
                         cudaFuncAttributeMaxDynamicSharedMemorySize, GEMM_SMEM);
    dim3 gemm_grid((n_nodes + BM - 1) / BM, 2);
    gemm_uv_mma<<<gemm_grid, 256, GEMM_SMEM>>>(z, W1, b1, n_nodes);

    edge_kernel<<<EDGE_BLOCKS, 256>>>(ei, W2, b2, out, n_edges, n_nodes);
}